// round 2
// baseline (speedup 1.0000x reference)
#include <cuda_runtime.h>
#include <math.h>

#define BATCH 64
#define PLEN  128
#define DIM   1024
#define ROWS  (BATCH * PLEN)

#define WARPS_PER_BLOCK   8
#define ROWS_PER_BLOCK    WARPS_PER_BLOCK              // one row per warp
#define NBLOCKS           (ROWS / ROWS_PER_BLOCK)      // 1024
#define BLOCKS_PER_BATCH  (PLEN / ROWS_PER_BLOCK)      // 16

// Scratch: per-row attention score s and fc projection t, plus per-batch
// completion counters (zero-initialized; finisher resets to 0 each call,
// so state is identical across graph replays).
__device__ float g_s[ROWS];
__device__ float g_t[ROWS];
__device__ int   g_cnt[BATCH];

__global__ void __launch_bounds__(256)
fused_kernel(const float* __restrict__ h,
             const float* __restrict__ q,
             const float* __restrict__ W_att,
             const float* __restrict__ b_att,
             const float* __restrict__ W_fc,
             const float* __restrict__ b_fc,
             float* __restrict__ out) {
    const int warp = threadIdx.x >> 5;
    const int lane = threadIdx.x & 31;
    const int row  = blockIdx.x * ROWS_PER_BLOCK + warp;   // (b*PLEN + p)
    const int b    = blockIdx.x / BLOCKS_PER_BATCH;

    // ---- Phase 1: per-row dual dot product (warp-collective) ----
    const float4* h4 = reinterpret_cast<const float4*>(h + (size_t)row * DIM);
    const float4* q4 = reinterpret_cast<const float4*>(q + (size_t)row * DIM);
    const float4* wa = reinterpret_cast<const float4*>(W_att);  // 512 float4
    const float4* wf = reinterpret_cast<const float4*>(W_fc);

    float s = 0.f, t = 0.f;

    // h half: data from HBM, weights stay hot in L1 (16 KB total).
    #pragma unroll
    for (int i = 0; i < 8; ++i) {
        const int idx = lane + 32 * i;          // 0..255 (coalesced float4)
        const float4 v = h4[idx];
        const float4 a = wa[idx];
        const float4 f = wf[idx];
        s += v.x * a.x + v.y * a.y + v.z * a.z + v.w * a.w;
        t += v.x * f.x + v.y * f.y + v.z * f.z + v.w * f.w;
    }
    // q half
    #pragma unroll
    for (int i = 0; i < 8; ++i) {
        const int idx = lane + 32 * i;
        const float4 v = q4[idx];
        const float4 a = wa[256 + idx];
        const float4 f = wf[256 + idx];
        s += v.x * a.x + v.y * a.y + v.z * a.z + v.w * a.w;
        t += v.x * f.x + v.y * f.y + v.z * f.z + v.w * f.w;
    }

    // warp reduce (fixed order -> deterministic)
    #pragma unroll
    for (int off = 16; off > 0; off >>= 1) {
        s += __shfl_xor_sync(0xffffffffu, s, off);
        t += __shfl_xor_sync(0xffffffffu, t, off);
    }
    if (lane == 0) {
        __stcg(&g_s[row], s);   // L2-scope: visible to finisher block on another SM
        __stcg(&g_t[row], t);
    }

    // ---- Phase 2: last block of each batch does softmax + pool ----
    __syncthreads();
    __threadfence();            // make g_s/g_t writes visible before the atomic

    __shared__ int is_last;
    if (threadIdx.x == 0) {
        const int old = atomicAdd(&g_cnt[b], 1);
        is_last = (old == BLOCKS_PER_BATCH - 1);
    }
    __syncthreads();
    if (!is_last) return;

    const int p = threadIdx.x;  // 0..255; only 0..127 carry data
    float sv = -INFINITY, tv = 0.f;
    if (p < PLEN) {
        sv = __ldcg(&g_s[b * PLEN + p]) + b_att[0];
        tv = __ldcg(&g_t[b * PLEN + p]);
    }

    __shared__ float red[8];

    // block max over 8 warps (idle threads contribute -inf)
    float m = sv;
    #pragma unroll
    for (int off = 16; off > 0; off >>= 1)
        m = fmaxf(m, __shfl_xor_sync(0xffffffffu, m, off));
    if (lane == 0) red[warp] = m;
    __syncthreads();
    float bmax = red[0];
    #pragma unroll
    for (int w = 1; w < 8; ++w) bmax = fmaxf(bmax, red[w]);
    __syncthreads();

    const float e = (p < PLEN) ? expf(sv - bmax) : 0.f;
    float num = e * tv;
    float den = e;
    #pragma unroll
    for (int off = 16; off > 0; off >>= 1) {
        num += __shfl_xor_sync(0xffffffffu, num, off);
        den += __shfl_xor_sync(0xffffffffu, den, off);
    }
    __shared__ float rn[8];
    __shared__ float rd[8];
    if (lane == 0) { rn[warp] = num; rd[warp] = den; }
    __syncthreads();
    if (p == 0) {
        float N = 0.f, De = 0.f;
        #pragma unroll
        for (int w = 0; w < 8; ++w) { N += rn[w]; De += rd[w]; }
        out[b] = N / De + b_fc[0];
        g_cnt[b] = 0;           // reset for next call / graph replay
    }
}

extern "C" void kernel_launch(void* const* d_in, const int* in_sizes, int n_in,
                              void* d_out, int out_size) {
    const float* h     = (const float*)d_in[0];
    const float* q     = (const float*)d_in[1];
    const float* W_att = (const float*)d_in[2];
    const float* b_att = (const float*)d_in[3];
    const float* W_fc  = (const float*)d_in[4];
    const float* b_fc  = (const float*)d_in[5];
    float* out = (float*)d_out;

    fused_kernel<<<NBLOCKS, 32 * WARPS_PER_BLOCK>>>(h, q, W_att, b_att, W_fc, b_fc, out);
}